// round 13
// baseline (speedup 1.0000x reference)
#include <cuda_runtime.h>

// LNSLinear == y = x @ W^T + bias in fp32 (the LNS log/exp round-trip is
// algebraically the identity). fp32 tiled GEMM, packed-f32x2 FMA (FFMA2).
//
// x [512,512], w [512,512] (N-major, K contiguous), bias [512], out [512,512].

#define MDIM 512
#define NDIM 512
#define KDIM 512

#define BM 64
#define BN 32
#define BK 64
#define NTILES (KDIM / BK)

typedef unsigned long long u64;

#define FMA2(d, a, b, c) \
    asm("fma.rn.f32x2 %0, %1, %2, %3;" : "=l"(d) : "l"(a), "l"(b), "l"(c))

#define UNPACK2(lo, hi, v) \
    asm("mov.b64 {%0, %1}, %2;" : "=f"(lo), "=f"(hi) : "l"(v))

__global__ __launch_bounds__(256, 1)
void lns_linear_gemm(const float* __restrict__ x,
                     const float* __restrict__ w,
                     const float* __restrict__ bias,
                     float* __restrict__ out) {
    // k-major tiles, XOR-swizzled on (k>>2) to keep the transpose-store at
    // <=2-way bank conflicts while compute reads stay LDS.128-aligned.
    __shared__ __align__(16) float As[BK * BM];        // 16 KB
    __shared__ __align__(16) float Bsd[BK * BN * 2];   // 16 KB (duplicated pairs)

    const int t  = threadIdx.x;
    const int bm = blockIdx.y * BM;
    const int bn = blockIdx.x * BN;
    const int tx = t & 15;     // n-direction (2 outputs)
    const int ty = t >> 4;     // m-direction (4 outputs)

    const int q  = t & 15;     // k-quad index for staging loads (0..15)
    const int rb = t >> 4;     // row base for staging loads (0..15)

    // Staging global pointers (advance by BK per tile).
    const float* xg = x + (size_t)(bm + rb) * KDIM + q * 4;
    const float* wg = w + (size_t)(bn + rb) * KDIM + q * 4;

    // Prologue: load tile 0 into registers.
    float4 av[4], bv[2];
#pragma unroll
    for (int i = 0; i < 4; i++)
        av[i] = *(const float4*)(xg + (size_t)(16 * i) * KDIM);
#pragma unroll
    for (int i = 0; i < 2; i++)
        bv[i] = *(const float4*)(wg + (size_t)(16 * i) * KDIM);

    const float b0 = bias[bn + tx * 2];
    const float b1 = bias[bn + tx * 2 + 1];

    u64 acc00 = 0ull, acc01 = 0ull, acc10 = 0ull, acc11 = 0ull;

#pragma unroll 1
    for (int kt = 0; kt < NTILES; kt++) {
        // ---- stage registers -> smem (swizzled transpose) ----
#pragma unroll
        for (int i = 0; i < 4; i++) {
            int row = rb + 16 * i;
            int col = row ^ (q << 2);
            As[(4 * q + 0) * BM + col] = av[i].x;
            As[(4 * q + 1) * BM + col] = av[i].y;
            As[(4 * q + 2) * BM + col] = av[i].z;
            As[(4 * q + 3) * BM + col] = av[i].w;
        }
#pragma unroll
        for (int i = 0; i < 2; i++) {
            int row = rb + 16 * i;
            int c0  = (2 * row) ^ (q << 2);
            *(float2*)&Bsd[(4 * q + 0) * (2 * BN) + c0] = make_float2(bv[i].x, bv[i].x);
            *(float2*)&Bsd[(4 * q + 1) * (2 * BN) + c0] = make_float2(bv[i].y, bv[i].y);
            *(float2*)&Bsd[(4 * q + 2) * (2 * BN) + c0] = make_float2(bv[i].z, bv[i].z);
            *(float2*)&Bsd[(4 * q + 3) * (2 * BN) + c0] = make_float2(bv[i].w, bv[i].w);
        }
        __syncthreads();

        // ---- prefetch next tile into registers (hidden under compute) ----
        if (kt + 1 < NTILES) {
            xg += BK; wg += BK;
#pragma unroll
            for (int i = 0; i < 4; i++)
                av[i] = *(const float4*)(xg + (size_t)(16 * i) * KDIM);
#pragma unroll
            for (int i = 0; i < 2; i++)
                bv[i] = *(const float4*)(wg + (size_t)(16 * i) * KDIM);
        }

        // ---- compute: per k-step 2x LDS.128 + 4x FFMA2 (= 8 FMA) ----
#pragma unroll
        for (int k = 0; k < BK; k++) {
            int swz = (k >> 2) << 2;
            const ulonglong2 a =
                *(const ulonglong2*)&As[k * BM + ((ty * 4) ^ swz)];
            const ulonglong2 b =
                *(const ulonglong2*)&Bsd[k * (2 * BN) + ((tx * 4) ^ swz)];
            FMA2(acc00, a.x, b.x, acc00);   // rows m0,m0+1  col n0
            FMA2(acc10, a.y, b.x, acc10);   // rows m0+2,+3  col n0
            FMA2(acc01, a.x, b.y, acc01);   // rows m0,m0+1  col n0+1
            FMA2(acc11, a.y, b.y, acc11);   // rows m0+2,+3  col n0+1
        }
        __syncthreads();
    }

    // ---- epilogue: unpack, add bias, store float2 per row ----
    float a00l, a00h, a01l, a01h, a10l, a10h, a11l, a11h;
    UNPACK2(a00l, a00h, acc00);
    UNPACK2(a01l, a01h, acc01);
    UNPACK2(a10l, a10h, acc10);
    UNPACK2(a11l, a11h, acc11);

    const int m0 = bm + ty * 4;
    const int n0 = bn + tx * 2;
    float* o = out + (size_t)m0 * NDIM + n0;
    *(float2*)(o + 0 * NDIM) = make_float2(a00l + b0, a01l + b1);
    *(float2*)(o + 1 * NDIM) = make_float2(a00h + b0, a01h + b1);
    *(float2*)(o + 2 * NDIM) = make_float2(a10l + b0, a11l + b1);
    *(float2*)(o + 3 * NDIM) = make_float2(a10h + b0, a11h + b1);
}

extern "C" void kernel_launch(void* const* d_in, const int* in_sizes, int n_in,
                              void* d_out, int out_size) {
    const float* x    = (const float*)d_in[0];
    const float* w    = (const float*)d_in[1];
    const float* bias = (const float*)d_in[2];
    float* out        = (float*)d_out;

    dim3 grid(NDIM / BN, MDIM / BM);   // (16, 8) = 128 CTAs, one wave on 148 SMs
    lns_linear_gemm<<<grid, 256>>>(x, w, bias, out);
}